// round 10
// baseline (speedup 1.0000x reference)
#include <cuda_runtime.h>
#include <stdint.h>

// Problem constants
#define BSZ  16
#define SEQN 1024
#define NVV  512
#define DMM  256
#define KCL  8

// Tiling: block = 16 v x 128 d x full K. grid = 16b x 32vc x 2dh = 1024.
#define VT 16
#define DH 128
#define KB 16
#define NCH (SEQN / KB)       // 64
#define NPAIR 512

// -------- device scratch ---------------------------------------------------
__device__ float g_p[BSZ * NVV][9];     // dhalf-0 partials: norm^2 + 8 dots
__device__ int   g_flag[NPAIR];

typedef unsigned long long ull;

// -------- packed f32x2 helpers --------------------------------------------
__device__ __forceinline__ ull pack2(float x, float y) {
    ull r; asm("mov.b64 %0, {%1, %2};" : "=l"(r) : "f"(x), "f"(y)); return r;
}
__device__ __forceinline__ float2 unpk2(ull a) {
    float2 f; asm("mov.b64 {%0, %1}, %2;" : "=f"(f.x), "=f"(f.y) : "l"(a)); return f;
}
__device__ __forceinline__ void fma2(ull& d, ull a, ull b) {
    asm("fma.rn.f32x2 %0, %1, %2, %0;" : "+l"(d) : "l"(a), "l"(b));
}

// -------- JAX threefry2x32 (key = (0,7)), partitionable 32-bit fold -------
__device__ __forceinline__ uint32_t rotl32(uint32_t x, int r) {
    return (x << r) | (x >> (32 - r));
}
__device__ __forceinline__ uint32_t threefry_bits32(uint32_t c0, uint32_t c1) {
    const uint32_t ks0 = 0u, ks1 = 7u;
    const uint32_t ks2 = ks0 ^ ks1 ^ 0x1BD11BDAu;
    uint32_t x0 = c0 + ks0, x1 = c1 + ks1;
#define TFR(r) { x0 += x1; x1 = rotl32(x1, (r)); x1 ^= x0; }
    TFR(13) TFR(15) TFR(26) TFR(6)   x0 += ks1; x1 += ks2 + 1u;
    TFR(17) TFR(29) TFR(16) TFR(24)  x0 += ks2; x1 += ks0 + 2u;
    TFR(13) TFR(15) TFR(26) TFR(6)   x0 += ks0; x1 += ks1 + 3u;
    TFR(17) TFR(29) TFR(16) TFR(24)  x0 += ks1; x1 += ks2 + 4u;
    TFR(13) TFR(15) TFR(26) TFR(6)   x0 += ks2; x1 += ks0 + 5u;
#undef TFR
    return x0 ^ x1;
}

// -------- kernel 0: clear pair flags (each graph replay) -------------------
__global__ void zero_flags_kernel() {
    g_flag[threadIdx.x] = 0;
}

// -------- mega kernel ------------------------------------------------------
// 256 threads / 8 warps / 4 blocks per SM. Block tile: 16v x 128d x K=1024.
// Warp tile: 16v x 16d (warp w owns d-slice w*16). Thread: 2v x 4d.
//   vl = lane & 7  -> v = vl*2,  dl = lane >> 3 -> d = w*16 + dl*4.
// dhalf=0 block: GEMM -> 9-vector partials -> g_p + flag -> exit.
// dhalf=1 block: GEMM -> combine with partner -> sinkhorn -> bern -> write
//                its tile's 128 output rows (512 KB contiguous chunks).
__global__ __launch_bounds__(256, 4)
void mega_kernel(const float* __restrict__ x, const float* __restrict__ W,
                 const float* __restrict__ bias, const float* __restrict__ ce,
                 float4* __restrict__ out) {
    __shared__ __align__(16) float As[2][KB][VT];     // 2 KB
    __shared__ __align__(16) float Bs[2][KB][DH];     // 16 KB

    const int bid   = blockIdx.x;
    const int dhalf = bid & 1;
    const int vc    = (bid >> 1) & 31;
    const int b     = bid >> 6;
    const int v0    = vc * VT;
    const int d0    = dhalf * DH;
    const int pair  = bid >> 1;

    const int tid  = threadIdx.x;
    const int w    = tid >> 5;
    const int lane = tid & 31;
    const int vl   = lane & 7;            // v-group: v = vl*2
    const int dl   = lane >> 3;           // d-group: d = w*16 + dl*4
    const int dloc = w * 16 + dl * 4;

    const float* xb = x + (size_t)b * SEQN * NVV;

    // load roles
    const int axs = tid >> 2, axv = tid & 3;       // A: threads 0..63
    const int wdd = tid & 127, wsh = tid >> 7;     // B: all 256

    ull c2[2][2];
    c2[0][0] = 0ull; c2[0][1] = 0ull; c2[1][0] = 0ull; c2[1][1] = 0ull;

    // prefetch chunk 0
    float4 xa = make_float4(0.f, 0.f, 0.f, 0.f);
    if (tid < 64)
        xa = *(const float4*)(xb + (size_t)axs * NVV + v0 + axv * 4);
    float4 wa0 = *(const float4*)(W + (size_t)(d0 + wdd) * SEQN + wsh * 8);
    float4 wa1 = *(const float4*)(W + (size_t)(d0 + wdd) * SEQN + wsh * 8 + 4);

    if (tid < 64) *(float4*)&As[0][axs][axv * 4] = xa;
    {
        int sb = wsh * 8;
        Bs[0][sb + 0][wdd] = wa0.x; Bs[0][sb + 1][wdd] = wa0.y;
        Bs[0][sb + 2][wdd] = wa0.z; Bs[0][sb + 3][wdd] = wa0.w;
        Bs[0][sb + 4][wdd] = wa1.x; Bs[0][sb + 5][wdd] = wa1.y;
        Bs[0][sb + 6][wdd] = wa1.z; Bs[0][sb + 7][wdd] = wa1.w;
    }
    __syncthreads();

    for (int c = 0; c < NCH; ++c) {
        const int cur = c & 1;
        const int nxt = cur ^ 1;
        if (c + 1 < NCH) {
            int sn = (c + 1) * KB;
            if (tid < 64)
                xa = *(const float4*)(xb + (size_t)(sn + axs) * NVV + v0 + axv * 4);
            wa0 = *(const float4*)(W + (size_t)(d0 + wdd) * SEQN + sn + wsh * 8);
            wa1 = *(const float4*)(W + (size_t)(d0 + wdd) * SEQN + sn + wsh * 8 + 4);
        }

#pragma unroll
        for (int k = 0; k < KB; ++k) {
            float2 af = *(const float2*)&As[cur][k][vl * 2];
            ulonglong2 bb = *(const ulonglong2*)&Bs[cur][k][dloc];
            ull a0 = pack2(af.x, af.x);
            ull a1 = pack2(af.y, af.y);
            fma2(c2[0][0], a0, bb.x); fma2(c2[0][1], a0, bb.y);
            fma2(c2[1][0], a1, bb.x); fma2(c2[1][1], a1, bb.y);
        }

        if (c + 1 < NCH) {
            if (tid < 64) *(float4*)&As[nxt][axs][axv * 4] = xa;
            int sb = wsh * 8;
            Bs[nxt][sb + 0][wdd] = wa0.x; Bs[nxt][sb + 1][wdd] = wa0.y;
            Bs[nxt][sb + 2][wdd] = wa0.z; Bs[nxt][sb + 3][wdd] = wa0.w;
            Bs[nxt][sb + 4][wdd] = wa1.x; Bs[nxt][sb + 5][wdd] = wa1.y;
            Bs[nxt][sb + 6][wdd] = wa1.z; Bs[nxt][sb + 7][wdd] = wa1.w;
            __syncthreads();
        }
    }

    // ---- epilogue: cn norm + bias + per-v 9-vector partials ----
    __syncthreads();
    float* S      = &Bs[0][0][0];          // 4096 floats
    float* cn_s   = S;                     // [8][128] d-half slice
    float* bias_s = S + 1024;              // [128]
    float* red    = S + 1152;              // [8 warps][16 v][9] = 1152
    float* soft_s = S + 2304;              // [16][8]
    float* bvals  = S + 2432;              // [128]

    {   // warp w: full 256-d norm of cn row w, store 128-d slice
        const float* row = ce + w * DMM;
        float s = 0.f;
#pragma unroll
        for (int q = 0; q < DMM / 32; ++q) {
            float t = row[lane + q * 32];
            s += t * t;
        }
#pragma unroll
        for (int o = 16; o; o >>= 1) s += __shfl_xor_sync(0xffffffffu, s, o);
        float nrm = fmaxf(sqrtf(s), 1e-12f);
#pragma unroll
        for (int q = 0; q < DH / 32; ++q)
            cn_s[w * DH + lane + q * 32] = row[d0 + lane + q * 32] / nrm;
    }
    if (tid < DH) bias_s[tid] = bias[d0 + tid];
    __syncthreads();

#pragma unroll
    for (int vi = 0; vi < 2; ++vi) {
        float2 p0 = unpk2(c2[vi][0]);
        float2 p1 = unpk2(c2[vi][1]);
        float y0 = p0.x + bias_s[dloc + 0];
        float y1 = p0.y + bias_s[dloc + 1];
        float y2 = p1.x + bias_s[dloc + 2];
        float y3 = p1.y + bias_s[dloc + 3];

        float r[9];
        r[0] = y0 * y0 + y1 * y1 + y2 * y2 + y3 * y3;
#pragma unroll
        for (int kk = 0; kk < KCL; ++kk) {
            const float* cp = &cn_s[kk * DH + dloc];
            r[1 + kk] = y0 * cp[0] + y1 * cp[1] + y2 * cp[2] + y3 * cp[3];
        }
#pragma unroll
        for (int o = 8; o <= 16; o <<= 1) {
#pragma unroll
            for (int q = 0; q < 9; ++q)
                r[q] += __shfl_xor_sync(0xffffffffu, r[q], o);
        }
        if (dl == 0) {
            float* dst = red + ((size_t)w * VT + vl * 2 + vi) * 9;
#pragma unroll
            for (int q = 0; q < 9; ++q) dst[q] = r[q];
        }
    }
    __syncthreads();

    // threads 0..15: sum across 8 warps -> per-v 9-vector
    float acc[9];
    if (tid < VT) {
#pragma unroll
        for (int q = 0; q < 9; ++q) acc[q] = 0.f;
#pragma unroll
        for (int ww = 0; ww < 8; ++ww) {
            const float* src = red + ((size_t)ww * VT + tid) * 9;
#pragma unroll
            for (int q = 0; q < 9; ++q) acc[q] += src[q];
        }
    }

    if (dhalf == 0) {
        // publish partials + flag, exit early (frees SM slot)
        if (tid < VT) {
            float* dst = g_p[b * NVV + v0 + tid];
#pragma unroll
            for (int q = 0; q < 9; ++q) dst[q] = acc[q];
        }
        __syncthreads();
        if (tid == 0) {
            __threadfence();
            *((volatile int*)&g_flag[pair]) = 1;
        }
        return;
    }

    // ---- writer (dhalf==1): wait partner, combine, sinkhorn, bern, write --
    if (tid == 0) {
        volatile int* f = (volatile int*)&g_flag[pair];
        while (*f == 0) { __nanosleep(64); }
    }
    __syncthreads();
    __threadfence();

    if (tid < VT) {
        const float* pp = g_p[b * NVV + v0 + tid];
        float t9[9];
#pragma unroll
        for (int q = 0; q < 9; ++q) t9[q] = acc[q] + pp[q];
        float nrm = fmaxf(sqrtf(t9[0]), 1e-12f);
        float e[KCL], esum = 0.f;
#pragma unroll
        for (int kk = 0; kk < KCL; ++kk) {
            float prob = t9[1 + kk] / nrm;
            e[kk] = expf(prob / 0.05f);
            esum += e[kk];
        }
#pragma unroll
        for (int kk = 0; kk < KCL; ++kk) soft_s[tid * KCL + kk] = e[kk] / esum;
    }
    __syncthreads();

    if (tid < 128) {
        int kk = tid >> 4, v = tid & 15;
        int r = kk * (BSZ * NVV) + b * NVV + v0 + v;
        uint32_t bits = threefry_bits32(0u, (uint32_t)r);
        float f = __uint_as_float((bits >> 9) | 0x3f800000u) - 1.0f;
        float u = fmaxf(0.0f, f);
        bvals[tid] = (u < soft_s[v * KCL + kk]) ? 1.0f : 0.0f;
    }
    __syncthreads();

    // write 8 chunks of 16 contiguous rows (64 KB each)
#pragma unroll
    for (int kk = 0; kk < KCL; ++kk) {
        size_t base = (size_t)kk * (BSZ * NVV) + b * NVV + v0;
#pragma unroll
        for (int rr = 0; rr < VT; ++rr) {
            float v = bvals[kk * VT + rr];
            __stcs(&out[(base + rr) * 256 + tid], make_float4(v, v, v, v));
        }
    }
}

// -------- launch -----------------------------------------------------------
extern "C" void kernel_launch(void* const* d_in, const int* in_sizes, int n_in,
                              void* d_out, int out_size) {
    const float* x = nullptr;
    const float* W = nullptr;
    const float* bias = nullptr;
    const float* ce = nullptr;
    for (int i = 0; i < n_in; ++i) {
        switch (in_sizes[i]) {
            case BSZ * SEQN * NVV: x    = (const float*)d_in[i]; break;
            case DMM * SEQN:       W    = (const float*)d_in[i]; break;
            case DMM:              bias = (const float*)d_in[i]; break;
            case KCL * DMM:        ce   = (const float*)d_in[i]; break;
            default: break;
        }
    }
    float4* out = (float4*)d_out;

    zero_flags_kernel<<<1, NPAIR>>>();
    mega_kernel<<<2 * NPAIR, 256>>>(x, W, bias, ce, out);
    (void)out_size;
}

// round 11
// speedup vs baseline: 1.0903x; 1.0903x over previous
#include <cuda_runtime.h>
#include <stdint.h>

// Problem constants
#define BSZ  16
#define SEQN 1024
#define NVV  512
#define DMM  256
#define KCL  8

// Tiling: block = 16 v x 128 d x full K, 128 threads.
// grid = 16b x 32vc x 2dh = 1024 blocks, 8 blocks/SM -> single wave, 1.2% imbalance.
#define VT 16
#define DH 128
#define KB 16
#define NCH (SEQN / KB)       // 64
#define NPAIR 512

// -------- device scratch ---------------------------------------------------
__device__ float g_p[BSZ * NVV][9];     // dhalf-0 partials: norm^2 + 8 dots
__device__ int   g_flag[NPAIR];

typedef unsigned long long ull;

// -------- packed f32x2 helpers --------------------------------------------
__device__ __forceinline__ ull pack2(float x, float y) {
    ull r; asm("mov.b64 %0, {%1, %2};" : "=l"(r) : "f"(x), "f"(y)); return r;
}
__device__ __forceinline__ float2 unpk2(ull a) {
    float2 f; asm("mov.b64 {%0, %1}, %2;" : "=f"(f.x), "=f"(f.y) : "l"(a)); return f;
}
__device__ __forceinline__ void fma2(ull& d, ull a, ull b) {
    asm("fma.rn.f32x2 %0, %1, %2, %0;" : "+l"(d) : "l"(a), "l"(b));
}

// -------- JAX threefry2x32 (key = (0,7)), partitionable 32-bit fold -------
__device__ __forceinline__ uint32_t rotl32(uint32_t x, int r) {
    return (x << r) | (x >> (32 - r));
}
__device__ __forceinline__ uint32_t threefry_bits32(uint32_t c0, uint32_t c1) {
    const uint32_t ks0 = 0u, ks1 = 7u;
    const uint32_t ks2 = ks0 ^ ks1 ^ 0x1BD11BDAu;
    uint32_t x0 = c0 + ks0, x1 = c1 + ks1;
#define TFR(r) { x0 += x1; x1 = rotl32(x1, (r)); x1 ^= x0; }
    TFR(13) TFR(15) TFR(26) TFR(6)   x0 += ks1; x1 += ks2 + 1u;
    TFR(17) TFR(29) TFR(16) TFR(24)  x0 += ks2; x1 += ks0 + 2u;
    TFR(13) TFR(15) TFR(26) TFR(6)   x0 += ks0; x1 += ks1 + 3u;
    TFR(17) TFR(29) TFR(16) TFR(24)  x0 += ks1; x1 += ks2 + 4u;
    TFR(13) TFR(15) TFR(26) TFR(6)   x0 += ks2; x1 += ks0 + 5u;
#undef TFR
    return x0 ^ x1;
}

// -------- kernel 0: clear pair flags (each graph replay) -------------------
__global__ void zero_flags_kernel() {
    g_flag[threadIdx.x] = 0;
}

// -------- mega kernel ------------------------------------------------------
// 128 threads / 4 warps / 8 blocks per SM. Block tile: 16v x 128d x K=1024.
// Warp tile: 16v x 32d (warp w owns d-slice w*32). Thread: 4v x 4d.
//   vl = lane & 3 -> v = vl*4,  dl = lane >> 2 -> d = w*32 + dl*4.
// Per thread per k: 1 LDS.128 (A) + 1 LDS.128 (B) + 4 pack + 8 FFMA2.
// dhalf=0 block: GEMM -> 9-vector partials -> g_p + flag -> exit.
// dhalf=1 block: GEMM -> combine -> sinkhorn -> bern -> write 128 rows.
__global__ __launch_bounds__(128, 8)
void mega_kernel(const float* __restrict__ x, const float* __restrict__ W,
                 const float* __restrict__ bias, const float* __restrict__ ce,
                 float4* __restrict__ out) {
    __shared__ __align__(16) float As[2][KB][VT];     // 2 KB
    __shared__ __align__(16) float Bs[2][KB][DH];     // 16 KB

    const int bid   = blockIdx.x;
    const int dhalf = bid & 1;
    const int vc    = (bid >> 1) & 31;
    const int b     = bid >> 6;
    const int v0    = vc * VT;
    const int d0    = dhalf * DH;
    const int pair  = bid >> 1;

    const int tid  = threadIdx.x;
    const int w    = tid >> 5;
    const int lane = tid & 31;
    const int vl   = lane & 3;            // v = vl*4
    const int dl   = lane >> 2;           // d = w*32 + dl*4
    const int dloc = w * 32 + dl * 4;

    const float* xb = x + (size_t)b * SEQN * NVV;

    // load roles
    const int axs = tid >> 2, axv = tid & 3;       // A: threads 0..63
    const float* wrow = W + (size_t)(d0 + tid) * SEQN;   // B: one d-row each

    ull c2[4][2];
#pragma unroll
    for (int i = 0; i < 4; ++i) { c2[i][0] = 0ull; c2[i][1] = 0ull; }

    // prefetch chunk 0
    float4 xa = make_float4(0.f, 0.f, 0.f, 0.f);
    if (tid < 64)
        xa = *(const float4*)(xb + (size_t)axs * NVV + v0 + axv * 4);
    float4 wa0 = *(const float4*)(wrow + 0);
    float4 wa1 = *(const float4*)(wrow + 4);
    float4 wa2 = *(const float4*)(wrow + 8);
    float4 wa3 = *(const float4*)(wrow + 12);

    if (tid < 64) *(float4*)&As[0][axs][axv * 4] = xa;
    Bs[0][0][tid]  = wa0.x; Bs[0][1][tid]  = wa0.y;
    Bs[0][2][tid]  = wa0.z; Bs[0][3][tid]  = wa0.w;
    Bs[0][4][tid]  = wa1.x; Bs[0][5][tid]  = wa1.y;
    Bs[0][6][tid]  = wa1.z; Bs[0][7][tid]  = wa1.w;
    Bs[0][8][tid]  = wa2.x; Bs[0][9][tid]  = wa2.y;
    Bs[0][10][tid] = wa2.z; Bs[0][11][tid] = wa2.w;
    Bs[0][12][tid] = wa3.x; Bs[0][13][tid] = wa3.y;
    Bs[0][14][tid] = wa3.z; Bs[0][15][tid] = wa3.w;
    __syncthreads();

    for (int c = 0; c < NCH; ++c) {
        const int cur = c & 1;
        const int nxt = cur ^ 1;
        if (c + 1 < NCH) {
            int sn = (c + 1) * KB;
            if (tid < 64)
                xa = *(const float4*)(xb + (size_t)(sn + axs) * NVV + v0 + axv * 4);
            wa0 = *(const float4*)(wrow + sn + 0);
            wa1 = *(const float4*)(wrow + sn + 4);
            wa2 = *(const float4*)(wrow + sn + 8);
            wa3 = *(const float4*)(wrow + sn + 12);
        }

#pragma unroll
        for (int k = 0; k < KB; ++k) {
            float4 av = *(const float4*)&As[cur][k][vl * 4];
            ulonglong2 bb = *(const ulonglong2*)&Bs[cur][k][dloc];
            ull a0 = pack2(av.x, av.x);
            ull a1 = pack2(av.y, av.y);
            ull a2 = pack2(av.z, av.z);
            ull a3 = pack2(av.w, av.w);
            fma2(c2[0][0], a0, bb.x); fma2(c2[0][1], a0, bb.y);
            fma2(c2[1][0], a1, bb.x); fma2(c2[1][1], a1, bb.y);
            fma2(c2[2][0], a2, bb.x); fma2(c2[2][1], a2, bb.y);
            fma2(c2[3][0], a3, bb.x); fma2(c2[3][1], a3, bb.y);
        }

        if (c + 1 < NCH) {
            if (tid < 64) *(float4*)&As[nxt][axs][axv * 4] = xa;
            Bs[nxt][0][tid]  = wa0.x; Bs[nxt][1][tid]  = wa0.y;
            Bs[nxt][2][tid]  = wa0.z; Bs[nxt][3][tid]  = wa0.w;
            Bs[nxt][4][tid]  = wa1.x; Bs[nxt][5][tid]  = wa1.y;
            Bs[nxt][6][tid]  = wa1.z; Bs[nxt][7][tid]  = wa1.w;
            Bs[nxt][8][tid]  = wa2.x; Bs[nxt][9][tid]  = wa2.y;
            Bs[nxt][10][tid] = wa2.z; Bs[nxt][11][tid] = wa2.w;
            Bs[nxt][12][tid] = wa3.x; Bs[nxt][13][tid] = wa3.y;
            Bs[nxt][14][tid] = wa3.z; Bs[nxt][15][tid] = wa3.w;
            __syncthreads();
        }
    }

    // ---- epilogue ----
    __syncthreads();
    float* S      = &Bs[0][0][0];          // 4096+ floats available
    float* cn_s   = S;                     // [8][128] d-half slice
    float* bias_s = S + 1024;              // [128]
    float* red    = S + 1152;              // [4 warps][16 v][9] = 576
    float* soft_s = S + 1728;              // [16][8] = 128
    float* bvals  = S + 1856;              // [128]

    {   // 4 warps x 2 cn rows each: full 256-d norm, store 128-d slice
#pragma unroll
        for (int rr = 0; rr < 2; ++rr) {
            int ri = w * 2 + rr;
            const float* row = ce + ri * DMM;
            float s = 0.f;
#pragma unroll
            for (int q = 0; q < DMM / 32; ++q) {
                float t = row[lane + q * 32];
                s += t * t;
            }
#pragma unroll
            for (int o = 16; o; o >>= 1) s += __shfl_xor_sync(0xffffffffu, s, o);
            float nrm = fmaxf(sqrtf(s), 1e-12f);
#pragma unroll
            for (int q = 0; q < DH / 32; ++q)
                cn_s[ri * DH + lane + q * 32] = row[d0 + lane + q * 32] / nrm;
        }
    }
    bias_s[tid] = bias[d0 + tid];
    __syncthreads();

#pragma unroll
    for (int vi = 0; vi < 4; ++vi) {
        float2 p0 = unpk2(c2[vi][0]);
        float2 p1 = unpk2(c2[vi][1]);
        float y0 = p0.x + bias_s[dloc + 0];
        float y1 = p0.y + bias_s[dloc + 1];
        float y2 = p1.x + bias_s[dloc + 2];
        float y3 = p1.y + bias_s[dloc + 3];

        float r[9];
        r[0] = y0 * y0 + y1 * y1 + y2 * y2 + y3 * y3;
#pragma unroll
        for (int kk = 0; kk < KCL; ++kk) {
            const float* cp = &cn_s[kk * DH + dloc];
            r[1 + kk] = y0 * cp[0] + y1 * cp[1] + y2 * cp[2] + y3 * cp[3];
        }
#pragma unroll
        for (int o = 4; o <= 16; o <<= 1) {
#pragma unroll
            for (int q = 0; q < 9; ++q)
                r[q] += __shfl_xor_sync(0xffffffffu, r[q], o);
        }
        if (dl == 0) {      // lanes 0..3 hold vl = lane
            float* dst = red + ((size_t)w * VT + lane * 4 + vi) * 9;
#pragma unroll
            for (int q = 0; q < 9; ++q) dst[q] = r[q];
        }
    }
    __syncthreads();

    // threads 0..15: sum across 4 warps -> per-v 9-vector
    float acc[9];
    if (tid < VT) {
#pragma unroll
        for (int q = 0; q < 9; ++q)
            acc[q] = red[(0 * VT + tid) * 9 + q] + red[(1 * VT + tid) * 9 + q]
                   + red[(2 * VT + tid) * 9 + q] + red[(3 * VT + tid) * 9 + q];
    }

    if (dhalf == 0) {
        if (tid < VT) {
            float* dst = g_p[b * NVV + v0 + tid];
#pragma unroll
            for (int q = 0; q < 9; ++q) dst[q] = acc[q];
        }
        __syncthreads();
        if (tid == 0) {
            __threadfence();
            *((volatile int*)&g_flag[pair]) = 1;
        }
        return;
    }

    // ---- writer (dhalf==1): wait partner, combine, sinkhorn, bern, write --
    if (tid == 0) {
        volatile int* f = (volatile int*)&g_flag[pair];
        while (*f == 0) { __nanosleep(64); }
    }
    __syncthreads();
    __threadfence();

    if (tid < VT) {
        const float* pp = g_p[b * NVV + v0 + tid];
        float t9[9];
#pragma unroll
        for (int q = 0; q < 9; ++q) t9[q] = acc[q] + pp[q];
        float nrm = fmaxf(sqrtf(t9[0]), 1e-12f);
        float e[KCL], esum = 0.f;
#pragma unroll
        for (int kk = 0; kk < KCL; ++kk) {
            float prob = t9[1 + kk] / nrm;
            e[kk] = expf(prob / 0.05f);
            esum += e[kk];
        }
#pragma unroll
        for (int kk = 0; kk < KCL; ++kk) soft_s[tid * KCL + kk] = e[kk] / esum;
    }
    __syncthreads();

    {   // bern: one thread per (kk, v) = 8*16 = 128
        int kk = tid >> 4, v = tid & 15;
        int r = kk * (BSZ * NVV) + b * NVV + v0 + v;
        uint32_t bits = threefry_bits32(0u, (uint32_t)r);
        float f = __uint_as_float((bits >> 9) | 0x3f800000u) - 1.0f;
        float u = fmaxf(0.0f, f);
        bvals[tid] = (u < soft_s[v * KCL + kk]) ? 1.0f : 0.0f;
    }
    __syncthreads();

    // write 8 chunks of 16 contiguous rows (1KB rows, 128 threads x 2 stcs)
#pragma unroll
    for (int kk = 0; kk < KCL; ++kk) {
        size_t base = (size_t)kk * (BSZ * NVV) + b * NVV + v0;
#pragma unroll
        for (int rr = 0; rr < VT; ++rr) {
            float v = bvals[kk * VT + rr];
            float4 v4 = make_float4(v, v, v, v);
            __stcs(&out[(base + rr) * 256 + tid], v4);
            __stcs(&out[(base + rr) * 256 + 128 + tid], v4);
        }
    }
}

// -------- launch -----------------------------------------------------------
extern "C" void kernel_launch(void* const* d_in, const int* in_sizes, int n_in,
                              void* d_out, int out_size) {
    const float* x = nullptr;
    const float* W = nullptr;
    const float* bias = nullptr;
    const float* ce = nullptr;
    for (int i = 0; i < n_in; ++i) {
        switch (in_sizes[i]) {
            case BSZ * SEQN * NVV: x    = (const float*)d_in[i]; break;
            case DMM * SEQN:       W    = (const float*)d_in[i]; break;
            case DMM:              bias = (const float*)d_in[i]; break;
            case KCL * DMM:        ce   = (const float*)d_in[i]; break;
            default: break;
        }
    }
    float4* out = (float4*)d_out;

    zero_flags_kernel<<<1, NPAIR>>>();
    mega_kernel<<<2 * NPAIR, 128>>>(x, W, bias, ce, out);
    (void)out_size;
}

// round 12
// speedup vs baseline: 1.1864x; 1.0882x over previous
#include <cuda_runtime.h>
#include <stdint.h>

// Problem constants
#define BSZ  16
#define SEQN 1024
#define NVV  512
#define DMM  256
#define KCL  8

// Tiling: block = 16 v x 128 d x full K, 128 threads, 8 blocks/SM.
// grid = 16b x 32vc x 2dh = 1024 blocks -> single wave, ~1% imbalance.
#define VT 16
#define DH 128
#define KB 16
#define NCH (SEQN / KB)       // 64
#define NPAIR 512
#define BP (DH + 4)           // Bs row stride (floats): 16B-aligned, conflict-lite
#define AP (VT + 1)           // As2 row stride (ulls): kills 8-way STS conflict

// -------- device scratch ---------------------------------------------------
__device__ float g_p[BSZ * NVV][9];     // dhalf-0 partials: norm^2 + 8 dots
__device__ int   g_flag[NPAIR];

typedef unsigned long long ull;

// -------- packed f32x2 helpers --------------------------------------------
__device__ __forceinline__ ull pack2(float x, float y) {
    ull r; asm("mov.b64 %0, {%1, %2};" : "=l"(r) : "f"(x), "f"(y)); return r;
}
__device__ __forceinline__ float2 unpk2(ull a) {
    float2 f; asm("mov.b64 {%0, %1}, %2;" : "=f"(f.x), "=f"(f.y) : "l"(a)); return f;
}
__device__ __forceinline__ void fma2(ull& d, ull a, ull b) {
    asm("fma.rn.f32x2 %0, %1, %2, %0;" : "+l"(d) : "l"(a), "l"(b));
}

// -------- JAX threefry2x32 (key = (0,7)), partitionable 32-bit fold -------
__device__ __forceinline__ uint32_t rotl32(uint32_t x, int r) {
    return (x << r) | (x >> (32 - r));
}
__device__ __forceinline__ uint32_t threefry_bits32(uint32_t c0, uint32_t c1) {
    const uint32_t ks0 = 0u, ks1 = 7u;
    const uint32_t ks2 = ks0 ^ ks1 ^ 0x1BD11BDAu;
    uint32_t x0 = c0 + ks0, x1 = c1 + ks1;
#define TFR(r) { x0 += x1; x1 = rotl32(x1, (r)); x1 ^= x0; }
    TFR(13) TFR(15) TFR(26) TFR(6)   x0 += ks1; x1 += ks2 + 1u;
    TFR(17) TFR(29) TFR(16) TFR(24)  x0 += ks2; x1 += ks0 + 2u;
    TFR(13) TFR(15) TFR(26) TFR(6)   x0 += ks0; x1 += ks1 + 3u;
    TFR(17) TFR(29) TFR(16) TFR(24)  x0 += ks1; x1 += ks2 + 4u;
    TFR(13) TFR(15) TFR(26) TFR(6)   x0 += ks2; x1 += ks0 + 5u;
#undef TFR
    return x0 ^ x1;
}

// -------- kernel 0: clear pair flags (each graph replay) -------------------
__global__ void zero_flags_kernel() {
    g_flag[threadIdx.x] = 0;
}

// -------- mega kernel ------------------------------------------------------
// 128 threads / 4 warps / 8 blocks per SM. Block tile: 16v x 128d x K=1024.
// Warp tile: 16v x 32d. Thread: 4v x 4d (vl = lane&3, dl = lane>>2).
// Inner loop per k: 1 LDS.128 (B) + 4 LDS.64 (A f32x2 bcast) + 8 FFMA2.
// Tile loads: 4 consecutive lanes read one row's 64B -> nL=8 per warp LDG.
__global__ __launch_bounds__(128, 8)
void mega_kernel(const float* __restrict__ x, const float* __restrict__ W,
                 const float* __restrict__ bias, const float* __restrict__ ce,
                 float4* __restrict__ out) {
    __shared__ __align__(16) ull   As2[2][KB][AP];    // 4.25 KB (A duplicated)
    __shared__ __align__(16) float Bs[2][KB][BP];     // 16.5 KB

    const int bid   = blockIdx.x;
    const int dhalf = bid & 1;
    const int vc    = (bid >> 1) & 31;
    const int b     = bid >> 6;
    const int v0    = vc * VT;
    const int d0    = dhalf * DH;
    const int pair  = bid >> 1;

    const int tid  = threadIdx.x;
    const int w    = tid >> 5;
    const int lane = tid & 31;
    const int vl   = lane & 3;            // v = vl*4
    const int dl   = lane >> 2;           // d = w*32 + dl*4
    const int dloc = w * 32 + dl * 4;

    // load roles (coalesced: 4 lanes per row, 64B contiguous segments)
    const int lrow = tid >> 2;            // 0..31
    const int lq   = tid & 3;             // float4 index within 16-float seg
    // x tile: threads 0..63, s = lrow (0..15), q = lq
    const float* xp = x + ((size_t)b * SEQN + lrow) * NVV + v0 + lq * 4;
    // W tile: all threads, 4 rows each: row_i = lrow + 32*i
    const float* wp = W + (size_t)(d0 + lrow) * SEQN + lq * 4;

    ull c2[4][2];
#pragma unroll
    for (int i = 0; i < 4; ++i) { c2[i][0] = 0ull; c2[i][1] = 0ull; }

    // prefetch chunk 0
    float4 xa = make_float4(0.f, 0.f, 0.f, 0.f);
    if (tid < 64) xa = *(const float4*)(xp);
    float4 wa[4];
#pragma unroll
    for (int i = 0; i < 4; ++i)
        wa[i] = *(const float4*)(wp + (size_t)(32 * i) * SEQN);

    // commit chunk 0 -> buffer 0
    if (tid < 64) {
        As2[0][lrow][lq * 4 + 0] = pack2(xa.x, xa.x);
        As2[0][lrow][lq * 4 + 1] = pack2(xa.y, xa.y);
        As2[0][lrow][lq * 4 + 2] = pack2(xa.z, xa.z);
        As2[0][lrow][lq * 4 + 3] = pack2(xa.w, xa.w);
    }
#pragma unroll
    for (int i = 0; i < 4; ++i) {
        int row = lrow + 32 * i;
        Bs[0][lq * 4 + 0][row] = wa[i].x;
        Bs[0][lq * 4 + 1][row] = wa[i].y;
        Bs[0][lq * 4 + 2][row] = wa[i].z;
        Bs[0][lq * 4 + 3][row] = wa[i].w;
    }
    __syncthreads();

    for (int c = 0; c < NCH; ++c) {
        const int cur = c & 1;
        const int nxt = cur ^ 1;
        if (c + 1 < NCH) {
            int sn = (c + 1) * KB;
            if (tid < 64) xa = *(const float4*)(xp + (size_t)sn * NVV);
#pragma unroll
            for (int i = 0; i < 4; ++i)
                wa[i] = *(const float4*)(wp + (size_t)(32 * i) * SEQN + sn);
        }

#pragma unroll
        for (int k = 0; k < KB; ++k) {
            ulonglong2 bb = *(const ulonglong2*)&Bs[cur][k][dloc];
            const ull* ap = &As2[cur][k][vl * 4];
            ull a0 = ap[0], a1 = ap[1], a2 = ap[2], a3 = ap[3];
            fma2(c2[0][0], a0, bb.x); fma2(c2[0][1], a0, bb.y);
            fma2(c2[1][0], a1, bb.x); fma2(c2[1][1], a1, bb.y);
            fma2(c2[2][0], a2, bb.x); fma2(c2[2][1], a2, bb.y);
            fma2(c2[3][0], a3, bb.x); fma2(c2[3][1], a3, bb.y);
        }

        if (c + 1 < NCH) {
            if (tid < 64) {
                As2[nxt][lrow][lq * 4 + 0] = pack2(xa.x, xa.x);
                As2[nxt][lrow][lq * 4 + 1] = pack2(xa.y, xa.y);
                As2[nxt][lrow][lq * 4 + 2] = pack2(xa.z, xa.z);
                As2[nxt][lrow][lq * 4 + 3] = pack2(xa.w, xa.w);
            }
#pragma unroll
            for (int i = 0; i < 4; ++i) {
                int row = lrow + 32 * i;
                Bs[nxt][lq * 4 + 0][row] = wa[i].x;
                Bs[nxt][lq * 4 + 1][row] = wa[i].y;
                Bs[nxt][lq * 4 + 2][row] = wa[i].z;
                Bs[nxt][lq * 4 + 3][row] = wa[i].w;
            }
            __syncthreads();
        }
    }

    // ---- epilogue ----
    __syncthreads();
    float* S      = &Bs[0][0][0];
    float* cn_s   = S;                     // [8][128] d-half slice
    float* bias_s = S + 1024;              // [128]
    float* red    = S + 1152;              // [4 warps][16 v][9] = 576
    float* soft_s = S + 1728;              // [16][8]
    float* bvals  = S + 1856;              // [128]

    {   // 4 warps x 2 cn rows each: full 256-d norm, store 128-d slice
#pragma unroll
        for (int rr = 0; rr < 2; ++rr) {
            int ri = w * 2 + rr;
            const float* row = ce + ri * DMM;
            float s = 0.f;
#pragma unroll
            for (int q = 0; q < DMM / 32; ++q) {
                float t = row[lane + q * 32];
                s += t * t;
            }
#pragma unroll
            for (int o = 16; o; o >>= 1) s += __shfl_xor_sync(0xffffffffu, s, o);
            float nrm = fmaxf(sqrtf(s), 1e-12f);
#pragma unroll
            for (int q = 0; q < DH / 32; ++q)
                cn_s[ri * DH + lane + q * 32] = row[d0 + lane + q * 32] / nrm;
        }
    }
    bias_s[tid] = bias[d0 + tid];
    __syncthreads();

#pragma unroll
    for (int vi = 0; vi < 4; ++vi) {
        float2 p0 = unpk2(c2[vi][0]);
        float2 p1 = unpk2(c2[vi][1]);
        float y0 = p0.x + bias_s[dloc + 0];
        float y1 = p0.y + bias_s[dloc + 1];
        float y2 = p1.x + bias_s[dloc + 2];
        float y3 = p1.y + bias_s[dloc + 3];

        float r[9];
        r[0] = y0 * y0 + y1 * y1 + y2 * y2 + y3 * y3;
#pragma unroll
        for (int kk = 0; kk < KCL; ++kk) {
            const float* cp = &cn_s[kk * DH + dloc];
            r[1 + kk] = y0 * cp[0] + y1 * cp[1] + y2 * cp[2] + y3 * cp[3];
        }
#pragma unroll
        for (int o = 4; o <= 16; o <<= 1) {
#pragma unroll
            for (int q = 0; q < 9; ++q)
                r[q] += __shfl_xor_sync(0xffffffffu, r[q], o);
        }
        if (dl == 0) {      // lanes 0..3: vl == lane
            float* dst = red + ((size_t)w * VT + lane * 4 + vi) * 9;
#pragma unroll
            for (int q = 0; q < 9; ++q) dst[q] = r[q];
        }
    }
    __syncthreads();

    float acc[9];
    if (tid < VT) {
#pragma unroll
        for (int q = 0; q < 9; ++q)
            acc[q] = red[(0 * VT + tid) * 9 + q] + red[(1 * VT + tid) * 9 + q]
                   + red[(2 * VT + tid) * 9 + q] + red[(3 * VT + tid) * 9 + q];
    }

    if (dhalf == 0) {
        if (tid < VT) {
            float* dst = g_p[b * NVV + v0 + tid];
#pragma unroll
            for (int q = 0; q < 9; ++q) dst[q] = acc[q];
        }
        __syncthreads();
        if (tid == 0) {
            __threadfence();
            *((volatile int*)&g_flag[pair]) = 1;
        }
        return;
    }

    // ---- writer (dhalf==1): wait partner, combine, sinkhorn, bern, write --
    if (tid == 0) {
        volatile int* f = (volatile int*)&g_flag[pair];
        while (*f == 0) { __nanosleep(64); }
    }
    __syncthreads();
    __threadfence();

    if (tid < VT) {
        const float* pp = g_p[b * NVV + v0 + tid];
        float t9[9];
#pragma unroll
        for (int q = 0; q < 9; ++q) t9[q] = acc[q] + pp[q];
        float nrm = fmaxf(sqrtf(t9[0]), 1e-12f);
        float e[KCL], esum = 0.f;
#pragma unroll
        for (int kk = 0; kk < KCL; ++kk) {
            float prob = t9[1 + kk] / nrm;
            e[kk] = expf(prob / 0.05f);
            esum += e[kk];
        }
#pragma unroll
        for (int kk = 0; kk < KCL; ++kk) soft_s[tid * KCL + kk] = e[kk] / esum;
    }
    __syncthreads();

    {   // bern: one thread per (kk, v) = 8*16 = 128
        int kk = tid >> 4, v = tid & 15;
        int r = kk * (BSZ * NVV) + b * NVV + v0 + v;
        uint32_t bits = threefry_bits32(0u, (uint32_t)r);
        float f = __uint_as_float((bits >> 9) | 0x3f800000u) - 1.0f;
        float u = fmaxf(0.0f, f);
        bvals[tid] = (u < soft_s[v * KCL + kk]) ? 1.0f : 0.0f;
    }
    __syncthreads();

    // write 8 chunks of 16 contiguous rows (1KB rows, 128 threads x 2 stcs)
#pragma unroll
    for (int kk = 0; kk < KCL; ++kk) {
        size_t base = (size_t)kk * (BSZ * NVV) + b * NVV + v0;
#pragma unroll
        for (int rr = 0; rr < VT; ++rr) {
            float v = bvals[kk * VT + rr];
            float4 v4 = make_float4(v, v, v, v);
            __stcs(&out[(base + rr) * 256 + tid], v4);
            __stcs(&out[(base + rr) * 256 + 128 + tid], v4);
        }
    }
}

// -------- launch -----------------------------------------------------------
extern "C" void kernel_launch(void* const* d_in, const int* in_sizes, int n_in,
                              void* d_out, int out_size) {
    const float* x = nullptr;
    const float* W = nullptr;
    const float* bias = nullptr;
    const float* ce = nullptr;
    for (int i = 0; i < n_in; ++i) {
        switch (in_sizes[i]) {
            case BSZ * SEQN * NVV: x    = (const float*)d_in[i]; break;
            case DMM * SEQN:       W    = (const float*)d_in[i]; break;
            case DMM:              bias = (const float*)d_in[i]; break;
            case KCL * DMM:        ce   = (const float*)d_in[i]; break;
            default: break;
        }
    }
    float4* out = (float4*)d_out;

    zero_flags_kernel<<<1, NPAIR>>>();
    mega_kernel<<<2 * NPAIR, 128>>>(x, W, bias, ce, out);
    (void)out_size;
}

// round 13
// speedup vs baseline: 2.0121x; 1.6959x over previous
#include <cuda_runtime.h>
#include <stdint.h>

// Problem constants
#define BSZ  16
#define SEQN 1024
#define NVV  512
#define DMM  256
#define KCL  8

// Tiling: block = 32 v x 256 d x full K, 256 threads, 2 blocks/SM.
// grid = 16 b x 8 vc = 256 blocks.
#define VT 32
#define KB 16
#define NCH (SEQN / KB)       // 64
#define AP 36                 // As row stride (floats): 144B, 16B-aligned, no conflict
#define BP 260                // Bs row stride (floats): 1040B, 16B-aligned

typedef unsigned long long ull;

// -------- packed f32x2 helpers --------------------------------------------
__device__ __forceinline__ ull pack2(float x, float y) {
    ull r; asm("mov.b64 %0, {%1, %2};" : "=l"(r) : "f"(x), "f"(y)); return r;
}
__device__ __forceinline__ float2 unpk2(ull a) {
    float2 f; asm("mov.b64 {%0, %1}, %2;" : "=f"(f.x), "=f"(f.y) : "l"(a)); return f;
}
__device__ __forceinline__ void fma2(ull& d, ull a, ull b) {
    asm("fma.rn.f32x2 %0, %1, %2, %0;" : "+l"(d) : "l"(a), "l"(b));
}

// -------- JAX threefry2x32 (key = (0,7)), partitionable 32-bit fold -------
__device__ __forceinline__ uint32_t rotl32(uint32_t x, int r) {
    return (x << r) | (x >> (32 - r));
}
__device__ __forceinline__ uint32_t threefry_bits32(uint32_t c0, uint32_t c1) {
    const uint32_t ks0 = 0u, ks1 = 7u;
    const uint32_t ks2 = ks0 ^ ks1 ^ 0x1BD11BDAu;
    uint32_t x0 = c0 + ks0, x1 = c1 + ks1;
#define TFR(r) { x0 += x1; x1 = rotl32(x1, (r)); x1 ^= x0; }
    TFR(13) TFR(15) TFR(26) TFR(6)   x0 += ks1; x1 += ks2 + 1u;
    TFR(17) TFR(29) TFR(16) TFR(24)  x0 += ks2; x1 += ks0 + 2u;
    TFR(13) TFR(15) TFR(26) TFR(6)   x0 += ks0; x1 += ks1 + 3u;
    TFR(17) TFR(29) TFR(16) TFR(24)  x0 += ks1; x1 += ks2 + 4u;
    TFR(13) TFR(15) TFR(26) TFR(6)   x0 += ks2; x1 += ks0 + 5u;
#undef TFR
    return x0 ^ x1;
}

// -------- fused kernel -----------------------------------------------------
// 256 threads / 8 warps / 2 blocks per SM. Block tile: 32v x 256d x K=1024.
// Warp tile: 32v x 32d (warp w owns d-slice w*32). Thread: 4v x 8d.
//   vl = lane & 7 -> v = vl*4,  dl = lane >> 3 -> d = w*32 + dl*8.
// Inner loop per thread per k: 1 LDS.128 (A) + 2 LDS.128 (B) + 4 pack
//   + 16 FFMA2  -> 3 LDS wavefronts per 16 FFMA2 per warp.
// Tail: sinkhorn for the block's 32 v, threefry bern, write 256 output rows
// (1 MB) — no inter-block dependencies anywhere.
__global__ __launch_bounds__(256, 2)
void fused_kernel(const float* __restrict__ x, const float* __restrict__ W,
                  const float* __restrict__ bias, const float* __restrict__ ce,
                  float4* __restrict__ out) {
    __shared__ __align__(16) float As[2][KB][AP];   // 4.5 KB
    __shared__ __align__(16) float Bs[2][KB][BP];   // 32.5 KB

    const int b    = blockIdx.y;
    const int v0   = blockIdx.x * VT;
    const int tid  = threadIdx.x;
    const int w    = tid >> 5;
    const int lane = tid & 31;
    const int vl   = lane & 7;            // v = vl*4
    const int dl   = lane >> 3;           // d = w*32 + dl*8
    const int dloc = w * 32 + dl * 8;

    // load roles
    // x tile (threads 0..127): s = tid>>3 (16 rows), vq = tid&7 (float4 col)
    const int axs = tid >> 3, axv = tid & 7;
    const float* xp = x + ((size_t)b * SEQN + axs) * NVV + v0 + axv * 4;
    // W tile (all 256): 4 lanes per row, rows lrow + 64*i
    const int lrow = tid >> 2, lq = tid & 3;
    const float* wp = W + (size_t)lrow * SEQN + lq * 4;

    ull c2[4][4];
#pragma unroll
    for (int i = 0; i < 4; ++i)
#pragma unroll
        for (int q = 0; q < 4; ++q) c2[i][q] = 0ull;

    // prefetch chunk 0
    float4 xa = make_float4(0.f, 0.f, 0.f, 0.f);
    if (tid < 128) xa = *(const float4*)(xp);
    float4 wa[4];
#pragma unroll
    for (int i = 0; i < 4; ++i)
        wa[i] = *(const float4*)(wp + (size_t)(64 * i) * SEQN);

    // commit chunk 0 -> buffer 0
    if (tid < 128) *(float4*)&As[0][axs][axv * 4] = xa;
#pragma unroll
    for (int i = 0; i < 4; ++i) {
        int row = lrow + 64 * i;
        Bs[0][lq * 4 + 0][row] = wa[i].x;
        Bs[0][lq * 4 + 1][row] = wa[i].y;
        Bs[0][lq * 4 + 2][row] = wa[i].z;
        Bs[0][lq * 4 + 3][row] = wa[i].w;
    }
    __syncthreads();

    for (int c = 0; c < NCH; ++c) {
        const int cur = c & 1;
        const int nxt = cur ^ 1;
        if (c + 1 < NCH) {
            int sn = (c + 1) * KB;
            if (tid < 128) xa = *(const float4*)(xp + (size_t)sn * NVV);
#pragma unroll
            for (int i = 0; i < 4; ++i)
                wa[i] = *(const float4*)(wp + (size_t)(64 * i) * SEQN + sn);
        }

#pragma unroll
        for (int k = 0; k < KB; ++k) {
            float4 av = *(const float4*)&As[cur][k][vl * 4];
            ulonglong2 b01 = *(const ulonglong2*)&Bs[cur][k][dloc];
            ulonglong2 b23 = *(const ulonglong2*)&Bs[cur][k][dloc + 4];
            ull a0 = pack2(av.x, av.x);
            ull a1 = pack2(av.y, av.y);
            ull a2 = pack2(av.z, av.z);
            ull a3 = pack2(av.w, av.w);
            fma2(c2[0][0], a0, b01.x); fma2(c2[0][1], a0, b01.y);
            fma2(c2[0][2], a0, b23.x); fma2(c2[0][3], a0, b23.y);
            fma2(c2[1][0], a1, b01.x); fma2(c2[1][1], a1, b01.y);
            fma2(c2[1][2], a1, b23.x); fma2(c2[1][3], a1, b23.y);
            fma2(c2[2][0], a2, b01.x); fma2(c2[2][1], a2, b01.y);
            fma2(c2[2][2], a2, b23.x); fma2(c2[2][3], a2, b23.y);
            fma2(c2[3][0], a3, b01.x); fma2(c2[3][1], a3, b01.y);
            fma2(c2[3][2], a3, b23.x); fma2(c2[3][3], a3, b23.y);
        }

        if (c + 1 < NCH) {
            if (tid < 128) *(float4*)&As[nxt][axs][axv * 4] = xa;
#pragma unroll
            for (int i = 0; i < 4; ++i) {
                int row = lrow + 64 * i;
                Bs[nxt][lq * 4 + 0][row] = wa[i].x;
                Bs[nxt][lq * 4 + 1][row] = wa[i].y;
                Bs[nxt][lq * 4 + 2][row] = wa[i].z;
                Bs[nxt][lq * 4 + 3][row] = wa[i].w;
            }
            __syncthreads();
        }
    }

    // ---- epilogue: cn norm + bias + cosine + sinkhorn (all in-block) ----
    __syncthreads();
    float* S      = &Bs[0][0][0];          // 8320 floats available
    float* cn_s   = S;                     // [8][256]  = 2048
    float* bias_s = S + 2048;              // [256]
    float* red    = S + 2304;              // [8 warps][32 v][9] = 2304
    float* soft_s = S + 4608;              // [32][8]   = 256
    float* bvals  = S + 4864;              // [256]

    {   // warp w normalizes cn row w (full 256 d)
        const float* row = ce + w * DMM;
        float s = 0.f;
#pragma unroll
        for (int q = 0; q < DMM / 32; ++q) {
            float t = row[lane + q * 32];
            s += t * t;
        }
#pragma unroll
        for (int o = 16; o; o >>= 1) s += __shfl_xor_sync(0xffffffffu, s, o);
        float nrm = fmaxf(sqrtf(s), 1e-12f);
#pragma unroll
        for (int q = 0; q < DMM / 32; ++q)
            cn_s[w * DMM + lane + q * 32] = row[lane + q * 32] / nrm;
    }
    bias_s[tid] = bias[tid];
    __syncthreads();

#pragma unroll
    for (int vi = 0; vi < 4; ++vi) {      // 4 v per thread
        float y[8];
#pragma unroll
        for (int q = 0; q < 4; ++q) {
            float2 p = unpk2(c2[vi][q]);
            y[2 * q]     = p.x + bias_s[dloc + 2 * q];
            y[2 * q + 1] = p.y + bias_s[dloc + 2 * q + 1];
        }
        float r[9];
        r[0] = 0.f;
#pragma unroll
        for (int q = 0; q < 8; ++q) r[0] += y[q] * y[q];
#pragma unroll
        for (int kk = 0; kk < KCL; ++kk) {
            const float* cp = &cn_s[kk * DMM + dloc];
            float s = 0.f;
#pragma unroll
            for (int q = 0; q < 8; ++q) s += y[q] * cp[q];
            r[1 + kk] = s;
        }
        // reduce across dl (lane bits 3,4)
#pragma unroll
        for (int o = 8; o <= 16; o <<= 1) {
#pragma unroll
            for (int q = 0; q < 9; ++q)
                r[q] += __shfl_xor_sync(0xffffffffu, r[q], o);
        }
        if (dl == 0) {      // lanes 0..7: vl == lane
            float* dst = red + ((size_t)w * VT + lane * 4 + vi) * 9;
#pragma unroll
            for (int q = 0; q < 9; ++q) dst[q] = r[q];
        }
    }
    __syncthreads();

    if (tid < VT) {         // sum across 8 warps -> sinkhorn
        float acc[9];
#pragma unroll
        for (int q = 0; q < 9; ++q) acc[q] = 0.f;
#pragma unroll
        for (int ww = 0; ww < 8; ++ww) {
            const float* src = red + ((size_t)ww * VT + tid) * 9;
#pragma unroll
            for (int q = 0; q < 9; ++q) acc[q] += src[q];
        }
        float nrm = fmaxf(sqrtf(acc[0]), 1e-12f);
        float e[KCL], esum = 0.f;
#pragma unroll
        for (int kk = 0; kk < KCL; ++kk) {
            float prob = acc[1 + kk] / nrm;
            e[kk] = expf(prob / 0.05f);
            esum += e[kk];
        }
#pragma unroll
        for (int kk = 0; kk < KCL; ++kk) soft_s[tid * KCL + kk] = e[kk] / esum;
    }
    __syncthreads();

    {   // bern: one thread per (kk, v) = 8*32 = 256
        int kk = tid >> 5, v = tid & 31;
        int r = kk * (BSZ * NVV) + b * NVV + v0 + v;
        uint32_t bits = threefry_bits32(0u, (uint32_t)r);
        float f = __uint_as_float((bits >> 9) | 0x3f800000u) - 1.0f;
        float u = fmaxf(0.0f, f);
        bvals[tid] = (u < soft_s[v * KCL + kk]) ? 1.0f : 0.0f;
    }
    __syncthreads();

    // ---- write this block's 256 output rows (1 MB, 8 chunks of 128 KB) ----
#pragma unroll
    for (int kk = 0; kk < KCL; ++kk) {
        size_t base = (size_t)kk * (BSZ * NVV) + b * NVV + v0;
#pragma unroll
        for (int rr = 0; rr < VT; ++rr) {
            float v = bvals[kk * VT + rr];
            __stcs(&out[(base + rr) * 256 + tid], make_float4(v, v, v, v));
        }
    }
}

// -------- launch -----------------------------------------------------------
extern "C" void kernel_launch(void* const* d_in, const int* in_sizes, int n_in,
                              void* d_out, int out_size) {
    const float* x = nullptr;
    const float* W = nullptr;
    const float* bias = nullptr;
    const float* ce = nullptr;
    for (int i = 0; i < n_in; ++i) {
        switch (in_sizes[i]) {
            case BSZ * SEQN * NVV: x    = (const float*)d_in[i]; break;
            case DMM * SEQN:       W    = (const float*)d_in[i]; break;
            case DMM:              bias = (const float*)d_in[i]; break;
            case KCL * DMM:        ce   = (const float*)d_in[i]; break;
            default: break;
        }
    }
    float4* out = (float4*)d_out;

    fused_kernel<<<dim3(NVV / VT, BSZ), 256>>>(x, W, bias, ce, out);
    (void)out_size;
}